// round 7
// baseline (speedup 1.0000x reference)
#include <cuda_runtime.h>

// PrevEmbedding fused: out[b,t,:] = LN_src(gathered_row)*g+b + LN_emb(pos+type)*g+b
// - LN only the 2048 gathered rows (never the 32000x768 table)
// - float4 vectorized: H=768 -> 192 threads x 1 float4 per stream
// - int64/int32 id-dtype detection fused in-kernel (high-word probes, L1 broadcast)

#define HD     768
#define TPB    192          // HD/4 float4 lanes
#define NW     (TPB / 32)   // 6 warps
#define LN_EPS 1e-5f

__global__ __launch_bounds__(TPB)
void prev_embedding_kernel(
    const float* __restrict__ cv,        // [V, H]
    const float* __restrict__ ocr,       // [B, N, H]
    const int*   __restrict__ raw,       // [B*T] int32 view (maybe int64 data)
    const float* __restrict__ cv_g,
    const float* __restrict__ cv_b,
    const float* __restrict__ ocr_g,
    const float* __restrict__ ocr_b,
    const float* __restrict__ pos_emb,   // [T, H]
    const float* __restrict__ type_emb,  // [2, H]
    const float* __restrict__ emb_g,
    const float* __restrict__ emb_b,
    float* __restrict__ out,             // [B, T, H]
    int V, int N, int T)
{
    const int bt  = blockIdx.x;
    const int b   = bt / T;
    const int t   = bt - b * T;
    const int tid = threadIdx.x;

    // --- id dtype detection: int64 data viewed as int32 has zero odd words.
    // 4 probes => false-positive prob ~(1/32050)^4. Uniform loads, L1 broadcast.
    const bool is64 = ((raw[1] | raw[3] | raw[5] | raw[7]) == 0);
    const int  id   = is64 ? raw[2 * bt] : raw[bt];

    const float* src;
    const float* gam;
    const float* bet;
    if (id >= V) {
        int oi = id - V;
        if (oi > N - 1) oi = N - 1;
        src = ocr + ((long long)b * N + oi) * HD;
        gam = ocr_g; bet = ocr_b;
    } else {
        int ci = id;
        if (ci < 0) ci = 0;
        if (ci > V - 1) ci = V - 1;
        src = cv + (long long)ci * HD;
        gam = cv_g; bet = cv_b;
    }

    const int type_id = (t >= V) ? 1 : 0;   // faithful to reference (0 in practice)

    const float4* src4 = (const float4*)src;
    const float4* pe4  = (const float4*)(pos_emb + t * HD);
    const float4* te4  = (const float4*)(type_emb + type_id * HD);

    const float4 xv = src4[tid];
    const float4 pv = pe4[tid];
    const float4 tv = te4[tid];

    float4 p;
    p.x = pv.x + tv.x;  p.y = pv.y + tv.y;
    p.z = pv.z + tv.z;  p.w = pv.w + tv.w;

    float sx  = xv.x + xv.y + xv.z + xv.w;
    float sxx = xv.x*xv.x + xv.y*xv.y + xv.z*xv.z + xv.w*xv.w;
    float sp  = p.x + p.y + p.z + p.w;
    float spp = p.x*p.x + p.y*p.y + p.z*p.z + p.w*p.w;

    #pragma unroll
    for (int off = 16; off > 0; off >>= 1) {
        sx  += __shfl_xor_sync(0xFFFFFFFFu, sx,  off);
        sxx += __shfl_xor_sync(0xFFFFFFFFu, sxx, off);
        sp  += __shfl_xor_sync(0xFFFFFFFFu, sp,  off);
        spp += __shfl_xor_sync(0xFFFFFFFFu, spp, off);
    }

    __shared__ float sm[4][NW];
    const int wid = tid >> 5;
    const int lid = tid & 31;
    if (lid == 0) {
        sm[0][wid] = sx;  sm[1][wid] = sxx;
        sm[2][wid] = sp;  sm[3][wid] = spp;
    }
    __syncthreads();

    float tsx = 0.f, tsxx = 0.f, tsp = 0.f, tspp = 0.f;
    #pragma unroll
    for (int w = 0; w < NW; w++) {
        tsx  += sm[0][w];  tsxx += sm[1][w];
        tsp  += sm[2][w];  tspp += sm[3][w];
    }

    const float inv_h = 1.0f / (float)HD;
    const float mu_x  = tsx * inv_h;
    const float var_x = fmaxf(tsxx * inv_h - mu_x * mu_x, 0.f);
    const float rx    = rsqrtf(var_x + LN_EPS);
    const float mu_p  = tsp * inv_h;
    const float var_p = fmaxf(tspp * inv_h - mu_p * mu_p, 0.f);
    const float rp    = rsqrtf(var_p + LN_EPS);

    const float4 g4  = ((const float4*)gam)[tid];
    const float4 b4  = ((const float4*)bet)[tid];
    const float4 eg4 = ((const float4*)emb_g)[tid];
    const float4 eb4 = ((const float4*)emb_b)[tid];

    float4 o;
    o.x = (xv.x - mu_x) * rx * g4.x + b4.x + (p.x - mu_p) * rp * eg4.x + eb4.x;
    o.y = (xv.y - mu_x) * rx * g4.y + b4.y + (p.y - mu_p) * rp * eg4.y + eb4.y;
    o.z = (xv.z - mu_x) * rx * g4.z + b4.z + (p.z - mu_p) * rp * eg4.z + eb4.z;
    o.w = (xv.w - mu_x) * rx * g4.w + b4.w + (p.w - mu_p) * rp * eg4.w + eb4.w;

    ((float4*)(out + (long long)bt * HD))[tid] = o;
}

extern "C" void kernel_launch(void* const* d_in, const int* in_sizes, int n_in,
                              void* d_out, int out_size) {
    const float* cv       = (const float*)d_in[0];   // [V, H]
    const float* ocr      = (const float*)d_in[1];   // [B, N, H]
    const int*   ids_raw  = (const int*)d_in[2];     // [B, T] int32 or int64
    const float* cv_g     = (const float*)d_in[3];
    const float* cv_b     = (const float*)d_in[4];
    const float* ocr_g    = (const float*)d_in[5];
    const float* ocr_b    = (const float*)d_in[6];
    const float* pos_emb  = (const float*)d_in[7];   // [T, H]
    const float* type_emb = (const float*)d_in[8];   // [2, H]
    const float* emb_g    = (const float*)d_in[9];
    const float* emb_b    = (const float*)d_in[10];
    float* out = (float*)d_out;

    const int Hs = in_sizes[3];             // 768
    const int V  = in_sizes[0] / Hs;        // 32000
    const int T  = in_sizes[7] / Hs;        // 128
    const int BT = in_sizes[2];             // 2048
    const int B  = BT / T;                  // 16
    const int N  = in_sizes[1] / (B * Hs);  // 50

    prev_embedding_kernel<<<BT, TPB>>>(cv, ocr, ids_raw,
                                       cv_g, cv_b, ocr_g, ocr_b,
                                       pos_emb, type_emb, emb_g, emb_b,
                                       out, V, N, T);
}

// round 8
// speedup vs baseline: 1.4337x; 1.4337x over previous
#include <cuda_runtime.h>

// PrevEmbedding fused, warp-per-row:
//   out[row,:] = LN(gathered_row)*g+b + LN(pos_emb[t]+type_emb[ty])*eg+eb
// - LN only the 2048 gathered rows, never the 32000x768 table
// - 1 warp = 1 row: 6 float4 per lane (MLP=6), shuffle-only reduction
// - 512-thread CTAs, 16 rows each -> grid=128, single wave on 148 SMs
// - all 6 param vectors staged in smem once per CTA (kills redundant L1 traffic)

#define HD     768
#define TPB    512
#define RPC    16           // rows (warps) per CTA
#define V4     (HD / 4)     // 192 float4 per row
#define LN_EPS 1e-5f

__global__ __launch_bounds__(TPB)
void prev_embedding_kernel(
    const float* __restrict__ cv,        // [V, H]
    const float* __restrict__ ocr,       // [B, N, H]
    const int*   __restrict__ raw,       // [B*T] int32 view (maybe int64 data)
    const float* __restrict__ cv_g,
    const float* __restrict__ cv_b,
    const float* __restrict__ ocr_g,
    const float* __restrict__ ocr_b,
    const float* __restrict__ pos_emb,   // [T, H]
    const float* __restrict__ type_emb,  // [2, H]
    const float* __restrict__ emb_g,
    const float* __restrict__ emb_b,
    float* __restrict__ out,             // [B*T, H]
    int V, int N, int T, int BT)
{
    __shared__ float4 s_cvg[V4], s_cvb[V4], s_ocg[V4], s_ocb[V4], s_eg[V4], s_eb[V4];

    const int tid  = threadIdx.x;
    const int wid  = tid >> 5;
    const int lane = tid & 31;
    const int row  = blockIdx.x * RPC + wid;

    // Stage all parameter vectors into smem (once per CTA).
    if (tid < V4) {
        s_cvg[tid] = ((const float4*)cv_g)[tid];
        s_cvb[tid] = ((const float4*)cv_b)[tid];
        s_ocg[tid] = ((const float4*)ocr_g)[tid];
        s_ocb[tid] = ((const float4*)ocr_b)[tid];
        s_eg[tid]  = ((const float4*)emb_g)[tid];
        s_eb[tid]  = ((const float4*)emb_b)[tid];
    }

    float4 x[6], p[6];
    float mu_x, rx, mu_p, rp;
    bool use_ocr = false;

    if (row < BT) {
        // id dtype detection: int64 viewed as int32 has zero odd words.
        const bool is64 = ((raw[1] | raw[3] | raw[5] | raw[7]) == 0);
        const int  id   = is64 ? raw[2 * row] : raw[row];

        const int b = row / T;
        const int t = row - b * T;

        const float* src;
        use_ocr = (id >= V);
        if (use_ocr) {
            int oi = id - V;
            if (oi > N - 1) oi = N - 1;
            src = ocr + ((long long)b * N + oi) * HD;
        } else {
            int ci = id < 0 ? 0 : (id > V - 1 ? V - 1 : id);
            src = cv + (long long)ci * HD;
        }

        const int type_id = (t >= V) ? 1 : 0;  // faithful to reference (0 here)
        const float4* s4  = (const float4*)src;
        const float4* pe4 = (const float4*)(pos_emb + t * HD);
        const float4* te4 = (const float4*)(type_emb + type_id * HD);

        // 6 independent gather loads per lane (MLP=6), then pos/type.
        #pragma unroll
        for (int j = 0; j < 6; j++) x[j] = s4[lane + 32 * j];
        #pragma unroll
        for (int j = 0; j < 6; j++) {
            float4 a = pe4[lane + 32 * j];
            float4 c = te4[lane + 32 * j];
            p[j] = make_float4(a.x + c.x, a.y + c.y, a.z + c.z, a.w + c.w);
        }

        float sx = 0.f, sxx = 0.f, sp = 0.f, spp = 0.f;
        #pragma unroll
        for (int j = 0; j < 6; j++) {
            sx  += x[j].x + x[j].y + x[j].z + x[j].w;
            sxx += x[j].x*x[j].x + x[j].y*x[j].y + x[j].z*x[j].z + x[j].w*x[j].w;
            sp  += p[j].x + p[j].y + p[j].z + p[j].w;
            spp += p[j].x*p[j].x + p[j].y*p[j].y + p[j].z*p[j].z + p[j].w*p[j].w;
        }

        #pragma unroll
        for (int off = 16; off > 0; off >>= 1) {
            sx  += __shfl_xor_sync(0xFFFFFFFFu, sx,  off);
            sxx += __shfl_xor_sync(0xFFFFFFFFu, sxx, off);
            sp  += __shfl_xor_sync(0xFFFFFFFFu, sp,  off);
            spp += __shfl_xor_sync(0xFFFFFFFFu, spp, off);
        }

        const float inv_h = 1.0f / (float)HD;
        mu_x = sx * inv_h;
        rx   = rsqrtf(fmaxf(sxx * inv_h - mu_x * mu_x, 0.f) + LN_EPS);
        mu_p = sp * inv_h;
        rp   = rsqrtf(fmaxf(spp * inv_h - mu_p * mu_p, 0.f) + LN_EPS);
    }

    __syncthreads();   // smem params ready (all threads reach this)

    if (row < BT) {
        const float4* gm = use_ocr ? s_ocg : s_cvg;
        const float4* bm = use_ocr ? s_ocb : s_cvb;
        float4* o = (float4*)(out + (long long)row * HD);

        #pragma unroll
        for (int j = 0; j < 6; j++) {
            const int h = lane + 32 * j;
            const float4 g  = gm[h];
            const float4 bb = bm[h];
            const float4 eg = s_eg[h];
            const float4 eb = s_eb[h];
            float4 r;
            r.x = (x[j].x - mu_x) * rx * g.x + bb.x + (p[j].x - mu_p) * rp * eg.x + eb.x;
            r.y = (x[j].y - mu_x) * rx * g.y + bb.y + (p[j].y - mu_p) * rp * eg.y + eb.y;
            r.z = (x[j].z - mu_x) * rx * g.z + bb.z + (p[j].z - mu_p) * rp * eg.z + eb.z;
            r.w = (x[j].w - mu_x) * rx * g.w + bb.w + (p[j].w - mu_p) * rp * eg.w + eb.w;
            o[h] = r;
        }
    }
}

extern "C" void kernel_launch(void* const* d_in, const int* in_sizes, int n_in,
                              void* d_out, int out_size) {
    const float* cv       = (const float*)d_in[0];   // [V, H]
    const float* ocr      = (const float*)d_in[1];   // [B, N, H]
    const int*   ids_raw  = (const int*)d_in[2];     // [B, T] int32 or int64
    const float* cv_g     = (const float*)d_in[3];
    const float* cv_b     = (const float*)d_in[4];
    const float* ocr_g    = (const float*)d_in[5];
    const float* ocr_b    = (const float*)d_in[6];
    const float* pos_emb  = (const float*)d_in[7];   // [T, H]
    const float* type_emb = (const float*)d_in[8];   // [2, H]
    const float* emb_g    = (const float*)d_in[9];
    const float* emb_b    = (const float*)d_in[10];
    float* out = (float*)d_out;

    const int Hs = in_sizes[3];             // 768
    const int V  = in_sizes[0] / Hs;        // 32000
    const int T  = in_sizes[7] / Hs;        // 128
    const int BT = in_sizes[2];             // 2048
    const int B  = BT / T;                  // 16
    const int N  = in_sizes[1] / (B * Hs);  // 50

    const int grid = (BT + RPC - 1) / RPC;  // 128
    prev_embedding_kernel<<<grid, TPB>>>(cv, ocr, ids_raw,
                                         cv_g, cv_b, ocr_g, ocr_b,
                                         pos_emb, type_emb, emb_g, emb_b,
                                         out, V, N, T, BT);
}

// round 10
// speedup vs baseline: 1.4760x; 1.0295x over previous
#include <cuda_runtime.h>

// PrevEmbedding fused, warp-per-row, barrier-free:
//   out[row,:] = LN(gathered_row)*g+b + LN(pos_emb[t]+type_emb[ty])*eg+eb
// - LN only the 2048 gathered rows, never the 32000x768 table
// - 1 warp = 1 row: 6 float4 per lane (MLP=6), shuffle-only reduction
// - 128-thread CTAs (4 rows), grid=512 -> all 148 SMs busy, no __syncthreads
// - params read via L1 (hit after first touch per SM), streaming output stores

#define HD     768
#define TPB    128
#define RPC    4            // rows (warps) per CTA
#define LN_EPS 1e-5f

__device__ __forceinline__ void stcs4(float4* p, float4 v) {
    asm volatile("st.global.cs.v4.f32 [%0], {%1,%2,%3,%4};"
                 :: "l"(p), "f"(v.x), "f"(v.y), "f"(v.z), "f"(v.w) : "memory");
}

__global__ __launch_bounds__(TPB)
void prev_embedding_kernel(
    const float* __restrict__ cv,        // [V, H]
    const float* __restrict__ ocr,       // [B, N, H]
    const int*   __restrict__ raw,       // [B*T] int32 view (maybe int64 data)
    const float* __restrict__ cv_g,
    const float* __restrict__ cv_b,
    const float* __restrict__ ocr_g,
    const float* __restrict__ ocr_b,
    const float* __restrict__ pos_emb,   // [T, H]
    const float* __restrict__ type_emb,  // [2, H]
    const float* __restrict__ emb_g,
    const float* __restrict__ emb_b,
    float* __restrict__ out,             // [B*T, H]
    int V, int N, int T, int BT)
{
    const int tid  = threadIdx.x;
    const int wid  = tid >> 5;
    const int lane = tid & 31;
    const int row  = blockIdx.x * RPC + wid;
    if (row >= BT) return;

    // id dtype detection: int64 viewed as int32 has zero odd words.
    // 4 uniform probes, L1 broadcast; FP prob ~(1/32050)^4.
    const bool is64 = ((raw[1] | raw[3] | raw[5] | raw[7]) == 0);
    const int  id   = is64 ? raw[2 * row] : raw[row];

    const int b = row / T;
    const int t = row - b * T;

    const float* src;
    const bool use_ocr = (id >= V);
    if (use_ocr) {
        int oi = id - V;
        if (oi > N - 1) oi = N - 1;
        src = ocr + ((long long)b * N + oi) * HD;
    } else {
        int ci = id < 0 ? 0 : (id > V - 1 ? V - 1 : id);
        src = cv + (long long)ci * HD;
    }

    const int type_id = (t >= V) ? 1 : 0;  // faithful to reference (0 here)
    const float4* s4  = (const float4*)src;
    const float4* pe4 = (const float4*)(pos_emb + t * HD);
    const float4* te4 = (const float4*)(type_emb + type_id * HD);

    // Front-batch all 18 loads: 6 gather (DRAM-latency) + 6 pos + 6 type (L2/L1).
    float4 x[6], p[6];
    #pragma unroll
    for (int j = 0; j < 6; j++) x[j] = s4[lane + 32 * j];
    #pragma unroll
    for (int j = 0; j < 6; j++) {
        float4 a = pe4[lane + 32 * j];
        float4 c = te4[lane + 32 * j];
        p[j] = make_float4(a.x + c.x, a.y + c.y, a.z + c.z, a.w + c.w);
    }

    float sx = 0.f, sxx = 0.f, sp = 0.f, spp = 0.f;
    #pragma unroll
    for (int j = 0; j < 6; j++) {
        sx  += x[j].x + x[j].y + x[j].z + x[j].w;
        sxx += x[j].x*x[j].x + x[j].y*x[j].y + x[j].z*x[j].z + x[j].w*x[j].w;
        sp  += p[j].x + p[j].y + p[j].z + p[j].w;
        spp += p[j].x*p[j].x + p[j].y*p[j].y + p[j].z*p[j].z + p[j].w*p[j].w;
    }

    #pragma unroll
    for (int off = 16; off > 0; off >>= 1) {
        sx  += __shfl_xor_sync(0xFFFFFFFFu, sx,  off);
        sxx += __shfl_xor_sync(0xFFFFFFFFu, sxx, off);
        sp  += __shfl_xor_sync(0xFFFFFFFFu, sp,  off);
        spp += __shfl_xor_sync(0xFFFFFFFFu, spp, off);
    }

    const float inv_h = 1.0f / (float)HD;
    const float mu_x = sx * inv_h;
    const float rx   = rsqrtf(fmaxf(sxx * inv_h - mu_x * mu_x, 0.f) + LN_EPS);
    const float mu_p = sp * inv_h;
    const float rp   = rsqrtf(fmaxf(spp * inv_h - mu_p * mu_p, 0.f) + LN_EPS);

    const float4* gm  = (const float4*)(use_ocr ? ocr_g : cv_g);
    const float4* bm  = (const float4*)(use_ocr ? ocr_b : cv_b);
    const float4* egm = (const float4*)emb_g;
    const float4* ebm = (const float4*)emb_b;
    float4* o = (float4*)(out + (long long)row * HD);

    #pragma unroll
    for (int j = 0; j < 6; j++) {
        const int h = lane + 32 * j;
        const float4 g  = gm[h];
        const float4 bb = bm[h];
        const float4 eg = egm[h];
        const float4 eb = ebm[h];
        float4 r;
        r.x = (x[j].x - mu_x) * rx * g.x + bb.x + (p[j].x - mu_p) * rp * eg.x + eb.x;
        r.y = (x[j].y - mu_x) * rx * g.y + bb.y + (p[j].y - mu_p) * rp * eg.y + eb.y;
        r.z = (x[j].z - mu_x) * rx * g.z + bb.z + (p[j].z - mu_p) * rp * eg.z + eb.z;
        r.w = (x[j].w - mu_x) * rx * g.w + bb.w + (p[j].w - mu_p) * rp * eg.w + eb.w;
        stcs4(o + h, r);
    }
}

extern "C" void kernel_launch(void* const* d_in, const int* in_sizes, int n_in,
                              void* d_out, int out_size) {
    const float* cv       = (const float*)d_in[0];   // [V, H]
    const float* ocr      = (const float*)d_in[1];   // [B, N, H]
    const int*   ids_raw  = (const int*)d_in[2];     // [B, T] int32 or int64
    const float* cv_g     = (const float*)d_in[3];
    const float* cv_b     = (const float*)d_in[4];
    const float* ocr_g    = (const float*)d_in[5];
    const float* ocr_b    = (const float*)d_in[6];
    const float* pos_emb  = (const float*)d_in[7];   // [T, H]
    const float* type_emb = (const float*)d_in[8];   // [2, H]
    const float* emb_g    = (const float*)d_in[9];
    const float* emb_b    = (const float*)d_in[10];
    float* out = (float*)d_out;

    const int Hs = in_sizes[3];             // 768
    const int V  = in_sizes[0] / Hs;        // 32000
    const int T  = in_sizes[7] / Hs;        // 128
    const int BT = in_sizes[2];             // 2048
    const int B  = BT / T;                  // 16
    const int N  = in_sizes[1] / (B * Hs);  // 50

    const int grid = (BT + RPC - 1) / RPC;  // 512
    prev_embedding_kernel<<<grid, TPB>>>(cv, ocr, ids_raw,
                                         cv_g, cv_b, ocr_g, ocr_b,
                                         pos_emb, type_emb, emb_g, emb_b,
                                         out, V, N, T, BT);
}